// round 8
// baseline (speedup 1.0000x reference)
#include <cuda_runtime.h>
#include <math.h>

// Problem dims
#define B_ 128
#define T_ 256
#define D_ 128
#define Z_ 64
#define E_ 512          // hidden size for all 4 LSTMs (E == DC)
#define NCOL 2048       // 4 * E_
#define KT 32           // K-tile

#define NCTA 128
#define NTHREADS 256

// ---------------- scratch layout (floats) ----------------
#define HB 65536                    // one h/c state buffer (128*512)
#define OFF_BAR 0                   // barrier state (zeroed every replay)
#define OFF_STATE 64
#define OFF_EH0 (OFF_STATE)         // 2 buffers (ping-pong)
#define OFF_EH1 (OFF_EH0 + 2*HB)
#define OFF_DH0 (OFF_EH1 + 2*HB)
#define OFF_DH1 (OFF_DH0 + 2*HB)
#define OFF_EC0 (OFF_DH1 + 2*HB)
#define OFF_EC1 (OFF_EC0 + HB)
#define OFF_DC0 (OFF_EC1 + HB)
#define OFF_DC1 (OFF_DC0 + HB)
#define STATE_END (OFF_DC1 + HB)    // memset covers [0, STATE_END)
#define OFF_GU1 STATE_END           // raw U-gate sums, 128*2048 each
#define OFF_GUD0 (OFF_GU1 + 262144)
#define OFF_GUD1 (OFF_GUD0 + 262144)
#define OFF_ENCIN (OFF_GUD1 + 262144)   // 128*256
#define OFF_ZBUF (OFF_ENCIN + 32768)    // 128*64
#define SCRATCH_TOTAL (OFF_ZBUF + 8192)

__device__ float g_scratch[SCRATCH_TOTAL];

__device__ __forceinline__ float sigf(float x) { return 1.0f / (1.0f + expf(-x)); }

// All kernel arguments in one struct (single kernelParams entry for the
// cooperative-launch path).
struct VaeParams {
    const float *x, *eps;
    const float *enc0_W, *enc0_U, *enc0_b;
    const float *enc1_W, *enc1_U, *enc1_b;
    const float *mu_W, *mu_b, *sig_W, *sig_b;
    const float *dec0_W, *dec0_U, *dec0_b;
    const float *dec1_W, *dec1_U, *dec1_b;
    const float *out_W, *out_b;
    float *o_dec, *o_sig, *o_mu, *o_ls, *o_z;
};

// ---------------------------------------------------------------------------
// Grid barrier. State (cnt, gen) zeroed by the memset node on every replay.
// gpu-scope __threadfence on both sides orders stores and invalidates L1D
// (CCTL.IVALL) so cross-SM data written before the barrier is seen after it.
// Co-residency of all 128 CTAs is guaranteed by the cooperative launch.
// ---------------------------------------------------------------------------
__device__ __forceinline__ void grid_sync(int& lgen)
{
    int* bar = (int*)g_scratch;            // [0]=cnt, [1]=gen
    __threadfence();
    __syncthreads();
    if (threadIdx.x == 0) {
        volatile int* gen = bar + 1;
        int g = lgen;
        if (atomicAdd(bar, 1) == NCTA - 1) {
            *bar = 0;
            __threadfence();
            atomicExch((int*)(bar + 1), g + 1);
        } else {
            while (*gen <= g) { __nanosleep(64); }
        }
    }
    __syncthreads();
    __threadfence();
    lgen++;
}

// ---------------------------------------------------------------------------
// Gate-GEMM tile, ROWS x 32 units (x4 gates), 256 threads.
// ROWS=32: warp owns 4 rows (FFMA/LDS balanced); ROWS=16: warp owns 2 rows.
// Up to two input segments. Gate-grouped W layout: coalesced LDG, 1-phase LDS.
// ---------------------------------------------------------------------------
template<int ROWS>
__device__ __forceinline__ void gemm_tile_t(
    const float* __restrict__ a1, const float* __restrict__ W1, int K1,
    const float* __restrict__ a2, const float* __restrict__ W2, int K2,
    int j0, int b0, float (*acc)[4],
    float (*w_s)[128], float (*a_s)[KT])
{
    const int tid = threadIdx.x;
    const int ux  = tid & 31;
    const int rg  = tid >> 5;
    constexpr int RW = ROWS / 8;

    for (int seg = 0; seg < 2; seg++) {
        const float* a = seg ? a2 : a1;
        const float* W = seg ? W2 : W1;
        const int K    = seg ? K2 : K1;
        if (K == 0) break;
        for (int k0 = 0; k0 < K; k0 += KT) {
            #pragma unroll
            for (int i = 0; i < 16; i++) {
                int idx = tid + i * 256;
                int kk = idx >> 7;
                int lc = idx & 127;
                w_s[kk][lc] = W[(k0 + kk) * NCOL + ((lc >> 5) * E_ + j0 + (lc & 31))];
            }
            #pragma unroll
            for (int i = 0; i < (ROWS * KT) / NTHREADS; i++) {
                int idx = tid + i * 256;
                a_s[idx >> 5][idx & 31] = a[(b0 + (idx >> 5)) * K + k0 + (idx & 31)];
            }
            __syncthreads();
            #pragma unroll
            for (int kk = 0; kk < KT; kk++) {
                float av[RW];
                #pragma unroll
                for (int r = 0; r < RW; r++) av[r] = a_s[rg * RW + r][kk];
                #pragma unroll
                for (int g = 0; g < 4; g++) {
                    float w = w_s[kk][g * 32 + ux];
                    #pragma unroll
                    for (int r = 0; r < RW; r++) acc[r][g] += av[r] * w;
                }
            }
            __syncthreads();
        }
    }
}

// LSTM pointwise epilogue for RW rows owned by this thread.
template<int RW>
__device__ __forceinline__ void lstm_epi(
    float (*acc)[4], const float* __restrict__ bias,
    const float* __restrict__ pregate,
    float* __restrict__ h_out, float* __restrict__ c_state,
    int j, int brow0)
{
    float b_i = bias[0 * E_ + j];
    float b_f = bias[1 * E_ + j];
    float b_c = bias[2 * E_ + j];
    float b_o = bias[3 * E_ + j];
    #pragma unroll
    for (int r = 0; r < RW; r++) {
        int b = brow0 + r;
        float pi = acc[r][0] + b_i;
        float pf = acc[r][1] + b_f;
        float pc = acc[r][2] + b_c;
        float po = acc[r][3] + b_o;
        if (pregate) {
            const float* pg = pregate + b * NCOL + j;
            pi += pg[0 * E_]; pf += pg[1 * E_];
            pc += pg[2 * E_]; po += pg[3 * E_];
        }
        float ig = sigf(pi);
        float fg = sigf(pf);
        float cg = tanhf(pc);
        float og = sigf(po);
        float cn = fg * c_state[b * E_ + j] + ig * cg;
        c_state[b * E_ + j] = cn;
        h_out[b * E_ + j]   = og * tanhf(cn);
    }
}

// Shared 16-row finish phase (enc1 / dec0 / dec1): one code copy for I$.
__device__ __noinline__ void finish16_phase(
    const float* __restrict__ a, const float* __restrict__ W, int K,
    const float* __restrict__ pregate, const float* __restrict__ bias,
    float* __restrict__ h_out, float* __restrict__ c_state,
    float (*w_s)[128], float (*a_s)[KT])
{
    const int cta = blockIdx.x;
    const int ux  = threadIdx.x & 31;
    const int rg  = threadIdx.x >> 5;
    const int j0  = (cta & 15) * 32;
    const int b0  = (cta >> 4) * 16;
    float acc[2][4] = {{0.f,0.f,0.f,0.f},{0.f,0.f,0.f,0.f}};
    gemm_tile_t<16>(a, W, K, nullptr, nullptr, 0, j0, b0, acc, w_s, a_s);
    lstm_epi<2>(acc, bias, pregate, h_out, c_state, j0 + ux, b0 + rg * 2);
}

// ---------------------------------------------------------------------------
// Persistent kernel: entire T=256 recurrence, 6 phases/step, grid barriers.
// ---------------------------------------------------------------------------
__global__ void __launch_bounds__(NTHREADS, 1) vae_persistent(VaeParams p)
{
    __shared__ float w_s[KT][128];
    __shared__ float a_s[32][KT];

    float* s = g_scratch;
    float* eh0[2] = { s + OFF_EH0, s + OFF_EH0 + HB };
    float* eh1[2] = { s + OFF_EH1, s + OFF_EH1 + HB };
    float* dh0[2] = { s + OFF_DH0, s + OFF_DH0 + HB };
    float* dh1[2] = { s + OFF_DH1, s + OFF_DH1 + HB };
    float* ec0  = s + OFF_EC0;
    float* ec1  = s + OFF_EC1;
    float* dc0  = s + OFF_DC0;
    float* dc1  = s + OFF_DC1;
    float* gU1  = s + OFF_GU1;
    float* gUd0 = s + OFF_GUD0;
    float* gUd1 = s + OFF_GUD1;
    float* encin = s + OFF_ENCIN;
    float* zbuf  = s + OFF_ZBUF;

    const int cta = blockIdx.x;
    const int tid = threadIdx.x;
    const int ux  = tid & 31;
    const int rg  = tid >> 5;
    int lgen = 0;

    // init: enc_in for t=0 (c_prev = 0 -> sigmoid = 0.5)
    {
        int idx = cta * NTHREADS + tid;      // 32768 threads, 16384 elems
        if (idx < B_ * D_) {
            int b = idx >> 7, j = idx & 127;
            float xn = p.x[(size_t)b * T_ * D_ + j];
            encin[b * 256 + j]       = xn;
            encin[b * 256 + 128 + j] = xn - 0.5f;
        }
    }
    grid_sync(lgen);

    for (int t = 0; t < T_; t++) {
        const int pp = t & 1, q = pp ^ 1;

        // ---- Phase A: 3 recurrent U-GEMMs + fused enc0 (256 tiles) ----
        #pragma unroll 1
        for (int tile = cta; tile < 256; tile += NCTA) {
            const int z  = tile >> 6;
            const int j0 = (tile & 15) * 32;
            const int b0 = ((tile >> 4) & 3) * 32;
            float acc[4][4];
            #pragma unroll
            for (int r = 0; r < 4; r++)
                #pragma unroll
                for (int g = 0; g < 4; g++) acc[r][g] = 0.f;

            const float *ga1, *gW1, *ga2, *gW2; int gK1, gK2;
            if (z == 0)      { ga1 = eh1[pp]; gW1 = p.enc1_U; gK1 = E_; ga2 = nullptr; gW2 = nullptr; gK2 = 0; }
            else if (z == 1) { ga1 = dh0[pp]; gW1 = p.dec0_U; gK1 = E_; ga2 = nullptr; gW2 = nullptr; gK2 = 0; }
            else if (z == 2) { ga1 = dh1[pp]; gW1 = p.dec1_U; gK1 = E_; ga2 = nullptr; gW2 = nullptr; gK2 = 0; }
            else             { ga1 = encin;   gW1 = p.enc0_W; gK1 = 256; ga2 = eh0[pp]; gW2 = p.enc0_U; gK2 = E_; }

            gemm_tile_t<32>(ga1, gW1, gK1, ga2, gW2, gK2, j0, b0, acc, w_s, a_s);

            const int j = j0 + ux;
            if (z < 3) {
                float* o = (z == 0) ? gU1 : (z == 1) ? gUd0 : gUd1;
                #pragma unroll
                for (int r = 0; r < 4; r++) {
                    int b = b0 + rg * 4 + r;
                    #pragma unroll
                    for (int g = 0; g < 4; g++)
                        o[b * NCOL + g * E_ + j] = acc[r][g];
                }
            } else {
                lstm_epi<4>(acc, p.enc0_b, nullptr, eh0[q], ec0, j, b0 + rg * 4);
            }
        }
        grid_sync(lgen);

        // ---- Phase B: enc1 finish (128 tiles, 16 rows) ----
        finish16_phase(eh0[q], p.enc1_W, E_, gU1, p.enc1_b, eh1[q], ec1, w_s, a_s);
        grid_sync(lgen);

        // ---- Phase C: latent (16 CTAs) ----
        if (cta < 16) {
            const int j0 = (cta & 1) * 32;
            const int b0 = (cta >> 1) * 16;
            float acc[2][2] = {{0.f,0.f},{0.f,0.f}};
            const float* a = eh1[q];
            for (int k0 = 0; k0 < E_; k0 += KT) {
                #pragma unroll
                for (int i = 0; i < 8; i++) {
                    int idx = tid + i * 256;
                    int kk = idx >> 6;
                    int lc = idx & 63;
                    int col = j0 + (lc & 31);
                    w_s[kk][lc] = (lc & 32) ? p.sig_W[(k0 + kk) * Z_ + col]
                                            : p.mu_W[(k0 + kk) * Z_ + col];
                }
                #pragma unroll
                for (int i = 0; i < 2; i++) {
                    int idx = tid + i * 256;
                    a_s[idx >> 5][idx & 31] = a[(b0 + (idx >> 5)) * E_ + k0 + (idx & 31)];
                }
                __syncthreads();
                #pragma unroll
                for (int kk = 0; kk < KT; kk++) {
                    float av0 = a_s[rg * 2 + 0][kk];
                    float av1 = a_s[rg * 2 + 1][kk];
                    float wm = w_s[kk][ux];
                    float ws = w_s[kk][32 + ux];
                    acc[0][0] += av0 * wm; acc[0][1] += av0 * ws;
                    acc[1][0] += av1 * wm; acc[1][1] += av1 * ws;
                }
                __syncthreads();
            }
            const int j = j0 + ux;
            #pragma unroll
            for (int r = 0; r < 2; r++) {
                int b = b0 + rg * 2 + r;
                float mu = acc[r][0] + p.mu_b[j];
                float ls = acc[r][1] + p.sig_b[j];
                float sg = expf(ls);
                float zv = mu + sg * p.eps[((size_t)t * B_ + b) * Z_ + j];
                size_t o = ((size_t)t * B_ + b) * Z_ + j;
                p.o_sig[o] = sg;
                p.o_mu[o]  = mu;
                p.o_ls[o]  = ls;
                p.o_z[o]   = zv;
                zbuf[b * Z_ + j] = zv;
            }
        }
        grid_sync(lgen);

        // ---- Phase D: dec0 finish (K=64) ----
        finish16_phase(zbuf, p.dec0_W, Z_, gUd0, p.dec0_b, dh0[q], dc0, w_s, a_s);
        grid_sync(lgen);

        // ---- Phase E: dec1 finish ----
        finish16_phase(dh0[q], p.dec1_W, E_, gUd1, p.dec1_b, dh1[q], dc1, w_s, a_s);
        grid_sync(lgen);

        // ---- Phase F: output + next-step enc_in (32 CTAs) ----
        if (cta < 32) {
            const int c0 = (cta & 3) * 32;
            const int b0 = (cta >> 2) * 16;
            float acc2[2] = {0.f, 0.f};
            const float* a = dh1[q];
            for (int k0 = 0; k0 < E_; k0 += KT) {
                #pragma unroll
                for (int i = 0; i < 4; i++) {
                    int idx = tid + i * 256;
                    int kk = idx >> 5;
                    int c  = idx & 31;
                    w_s[kk][c] = p.out_W[(k0 + kk) * D_ + c0 + c];
                }
                #pragma unroll
                for (int i = 0; i < 2; i++) {
                    int idx = tid + i * 256;
                    a_s[idx >> 5][idx & 31] = a[(b0 + (idx >> 5)) * E_ + k0 + (idx & 31)];
                }
                __syncthreads();
                #pragma unroll
                for (int kk = 0; kk < KT; kk++) {
                    float w = w_s[kk][ux];
                    acc2[0] += a_s[rg * 2 + 0][kk] * w;
                    acc2[1] += a_s[rg * 2 + 1][kk] * w;
                }
                __syncthreads();
            }
            const int j  = c0 + ux;
            const int tn = (t + 1 < T_) ? (t + 1) : t;
            #pragma unroll
            for (int r = 0; r < 2; r++) {
                int b = b0 + rg * 2 + r;
                float ct = sigf(acc2[r] + p.out_b[j]);
                p.o_dec[(size_t)b * T_ * D_ + (size_t)t * D_ + j] = ct;
                float xn = p.x[(size_t)b * T_ * D_ + (size_t)tn * D_ + j];
                encin[b * 256 + j]       = xn;
                encin[b * 256 + 128 + j] = xn - sigf(ct);  // sigmoid of stored c_t: matches ref
            }
        }
        grid_sync(lgen);
    }
}

extern "C" void kernel_launch(void* const* d_in, const int* in_sizes, int n_in,
                              void* d_out, int out_size)
{
    VaeParams p;
    p.x      = (const float*)d_in[0];
    p.eps    = (const float*)d_in[1];
    p.enc0_W = (const float*)d_in[2];
    p.enc0_U = (const float*)d_in[3];
    p.enc0_b = (const float*)d_in[4];
    p.enc1_W = (const float*)d_in[5];
    p.enc1_U = (const float*)d_in[6];
    p.enc1_b = (const float*)d_in[7];
    p.mu_W   = (const float*)d_in[8];
    p.mu_b   = (const float*)d_in[9];
    p.sig_W  = (const float*)d_in[10];
    p.sig_b  = (const float*)d_in[11];
    p.dec0_W = (const float*)d_in[12];
    p.dec0_U = (const float*)d_in[13];
    p.dec0_b = (const float*)d_in[14];
    p.dec1_W = (const float*)d_in[15];
    p.dec1_U = (const float*)d_in[16];
    p.dec1_b = (const float*)d_in[17];
    p.out_W  = (const float*)d_in[18];
    p.out_b  = (const float*)d_in[19];

    float* out = (float*)d_out;
    p.o_dec = out;                                      // [B,T,D]
    p.o_sig = out + (size_t)B_ * T_ * D_;               // [T,B,Z]
    p.o_mu  = p.o_sig + (size_t)T_ * B_ * Z_;
    p.o_ls  = p.o_mu  + (size_t)T_ * B_ * Z_;
    p.o_z   = p.o_ls  + (size_t)T_ * B_ * Z_;

    float* s = nullptr;
    cudaGetSymbolAddress((void**)&s, g_scratch);

    // zero barrier state + all h/c state buffers (re-runs on every replay)
    cudaMemsetAsync(s, 0, sizeof(float) * (size_t)STATE_END, 0);

    // Cooperative launch: guarantees co-residency of all 128 CTAs (the grid
    // barrier's requirement) or fails fast with an explicit error instead of
    // deadlocking. If the cooperative path is rejected (e.g. not supported
    // under capture), fall back to a plain launch of the identical kernel.
    void* kernelArgs[] = { (void*)&p };
    cudaError_t e = cudaLaunchCooperativeKernel(
        (void*)vae_persistent, dim3(NCTA), dim3(NTHREADS), kernelArgs, 0, (cudaStream_t)0);
    if (e != cudaSuccess) {
        (void)cudaGetLastError();   // clear sticky error
        vae_persistent<<<NCTA, NTHREADS>>>(p);
    }
}

// round 9
// speedup vs baseline: 1.3005x; 1.3005x over previous
#include <cuda_runtime.h>
#include <math.h>
#include <stdint.h>

// Problem dims
#define B_ 128
#define T_ 256
#define D_ 128
#define Z_ 64
#define E_ 512
#define NCOL 2048
#define KT 32

#define NCTA 128
#define NTHREADS 256

// ---------------- scratch layout (floats) ----------------
#define HB 65536
#define OFF_BAR 0
#define OFF_STATE 64
#define OFF_EH0 (OFF_STATE)
#define OFF_EH1 (OFF_EH0 + 2*HB)
#define OFF_DH0 (OFF_EH1 + 2*HB)
#define OFF_DH1 (OFF_DH0 + 2*HB)
#define OFF_EC0 (OFF_DH1 + 2*HB)
#define OFF_EC1 (OFF_EC0 + HB)
#define OFF_DC0 (OFF_EC1 + HB)
#define OFF_DC1 (OFF_DC0 + HB)
#define STATE_END (OFF_DC1 + HB)
#define OFF_GU1 STATE_END
#define OFF_GUD0 (OFF_GU1 + 262144)
#define OFF_GUD1 (OFF_GUD0 + 262144)
#define OFF_ENCIN (OFF_GUD1 + 262144)
#define OFF_ZBUF (OFF_ENCIN + 32768)
#define SCRATCH_TOTAL (OFF_ZBUF + 8192)

__device__ float g_scratch[SCRATCH_TOTAL];

__device__ __forceinline__ float sigf(float x) { return 1.0f / (1.0f + expf(-x)); }

// Packed f32x2 FMA (full-rate fp32 path on sm_103a; ptxas never auto-emits it)
#define FMA2(acc_, a_, b_) \
    asm("fma.rn.f32x2 %0, %1, %2, %0;" : "+l"(acc_) : "l"(a_), "l"(b_))

__device__ __forceinline__ unsigned long long splat2(float w) {
    unsigned long long r; unsigned int b = __float_as_uint(w);
    asm("mov.b64 %0, {%1, %1};" : "=l"(r) : "r"(b));
    return r;
}
__device__ __forceinline__ float lo2(unsigned long long v) { return __uint_as_float((unsigned)v); }
__device__ __forceinline__ float hi2(unsigned long long v) { return __uint_as_float((unsigned)(v >> 32)); }

struct VaeParams {
    const float *x, *eps;
    const float *enc0_W, *enc0_U, *enc0_b;
    const float *enc1_W, *enc1_U, *enc1_b;
    const float *mu_W, *mu_b, *sig_W, *sig_b;
    const float *dec0_W, *dec0_U, *dec0_b;
    const float *dec1_W, *dec1_U, *dec1_b;
    const float *out_W, *out_b;
    float *o_dec, *o_sig, *o_mu, *o_ls, *o_z;
};

// ---------------------------------------------------------------------------
// Grid barrier (state zeroed by the memset node every replay; co-residency
// guaranteed by cooperative launch, with plain-launch fallback).
// ---------------------------------------------------------------------------
__device__ __forceinline__ void grid_sync(int& lgen)
{
    int* bar = (int*)g_scratch;            // [0]=cnt, [1]=gen
    __threadfence();
    __syncthreads();
    if (threadIdx.x == 0) {
        volatile int* gen = bar + 1;
        int g = lgen;
        if (atomicAdd(bar, 1) == NCTA - 1) {
            *bar = 0;
            __threadfence();
            atomicExch((int*)(bar + 1), g + 1);
        } else {
            while (*gen <= g) { __nanosleep(64); }
        }
    }
    __syncthreads();
    __threadfence();
    lgen++;
}

// ---------------------------------------------------------------------------
// Phase-A GEMM: 64 rows x 128 cols (32 units x 4 gates) per CTA, 256 thr.
// Thread: 8 rows (4 f32x2 pairs) x 4 gates. Register-prefetch double buffer.
// a_s transposed [KT][64] with XOR swizzle on 4-float groups (2-way STS);
// w_s [KT][128] gate-grouped (conflict-free).
// ---------------------------------------------------------------------------
__device__ __forceinline__ void gemm64(
    const float* __restrict__ a1, const float* __restrict__ W1, int K1,
    const float* __restrict__ a2, const float* __restrict__ W2, int K2,
    int j0, int b0, unsigned long long acc[4][4],
    float* w_s, float* a_s)
{
    const int tid = threadIdx.x;
    const int ux  = tid & 31;
    const int rg  = tid >> 5;
    const int nt  = (K1 + K2) / KT;
    float wreg[16], areg[8];

    auto load_tile = [&](int t) {
        int kb = t * KT;
        const float* a = a1; const float* W = W1; int K = K1;
        if (kb >= K1) { a = a2; W = W2; K = K2; kb -= K1; }
        #pragma unroll
        for (int i = 0; i < 16; i++) {
            int idx = tid + i * 256;
            wreg[i] = W[(kb + (idx >> 7)) * NCOL + (((idx & 127) >> 5) * E_ + j0 + (idx & 31))];
        }
        #pragma unroll
        for (int i = 0; i < 8; i++) {
            int idx = tid + i * 256;
            areg[i] = a[(b0 + (idx >> 5)) * K + kb + (idx & 31)];
        }
    };

    load_tile(0);
    #pragma unroll 1
    for (int t = 0; t < nt; t++) {
        __syncthreads();
        #pragma unroll
        for (int i = 0; i < 16; i++) {
            int idx = tid + i * 256;
            w_s[(idx >> 7) * 128 + (idx & 127)] = wreg[i];
        }
        #pragma unroll
        for (int i = 0; i < 8; i++) {
            int idx = tid + i * 256;
            int kk = idx & 31, row = idx >> 5;
            a_s[kk * 64 + (((row >> 2) ^ (kk & 15)) << 2) + (row & 3)] = areg[i];
        }
        __syncthreads();
        if (t + 1 < nt) load_tile(t + 1);
        #pragma unroll 8
        for (int kk = 0; kk < KT; kk++) {
            const float* ak = a_s + kk * 64;
            const int sw = kk & 15;
            ulonglong2 A0 = *(const ulonglong2*)(ak + (((rg * 2 + 0) ^ sw) << 2));
            ulonglong2 A1 = *(const ulonglong2*)(ak + (((rg * 2 + 1) ^ sw) << 2));
            const float* wk = w_s + kk * 128 + ux;
            #pragma unroll
            for (int g = 0; g < 4; g++) {
                unsigned long long w2 = splat2(wk[g * 32]);
                FMA2(acc[0][g], A0.x, w2);
                FMA2(acc[1][g], A0.y, w2);
                FMA2(acc[2][g], A1.x, w2);
                FMA2(acc[3][g], A1.y, w2);
            }
        }
    }
}

// ---------------------------------------------------------------------------
// Finish stage: 16 rows x 128 cols per CTA (128 CTAs). Thread: 1 pair x 4
// gates. W-GEMM + pregate + bias + LSTM update. Register-prefetch buffered.
// ---------------------------------------------------------------------------
__device__ __noinline__ void finish16(
    const float* __restrict__ a, const float* __restrict__ W, int K,
    const float* __restrict__ pregate, const float* __restrict__ bias,
    float* __restrict__ h_out, float* __restrict__ c_state,
    float* w_s, float* a_s)
{
    const int tid = threadIdx.x;
    const int ux  = tid & 31;
    const int rg  = tid >> 5;
    const int cta = blockIdx.x;
    const int j0  = (cta & 15) * 32;
    const int b0  = (cta >> 4) * 16;
    const int nt  = K / KT;
    unsigned long long acc[4] = {0ull, 0ull, 0ull, 0ull};
    float wreg[16], areg[2];

    auto load_tile = [&](int t) {
        int kb = t * KT;
        #pragma unroll
        for (int i = 0; i < 16; i++) {
            int idx = tid + i * 256;
            wreg[i] = W[(kb + (idx >> 7)) * NCOL + (((idx & 127) >> 5) * E_ + j0 + (idx & 31))];
        }
        #pragma unroll
        for (int i = 0; i < 2; i++) {
            int idx = tid + i * 256;
            areg[i] = a[(b0 + (idx & 15)) * K + kb + (idx >> 4)];
        }
    };

    load_tile(0);
    #pragma unroll 1
    for (int t = 0; t < nt; t++) {
        __syncthreads();
        #pragma unroll
        for (int i = 0; i < 16; i++) {
            int idx = tid + i * 256;
            w_s[(idx >> 7) * 128 + (idx & 127)] = wreg[i];
        }
        #pragma unroll
        for (int i = 0; i < 2; i++) {
            int idx = tid + i * 256;
            int kk = idx >> 4, row = idx & 15;
            a_s[kk * 16 + (((row >> 2) ^ (kk & 3)) << 2) + (row & 3)] = areg[i];
        }
        __syncthreads();
        if (t + 1 < nt) load_tile(t + 1);
        #pragma unroll 8
        for (int kk = 0; kk < KT; kk++) {
            unsigned long long A = *(const unsigned long long*)(
                a_s + kk * 16 + ((((rg >> 1) ^ (kk & 3))) << 2) + ((rg & 1) << 1));
            const float* wk = w_s + kk * 128 + ux;
            #pragma unroll
            for (int g = 0; g < 4; g++) {
                unsigned long long w2 = splat2(wk[g * 32]);
                FMA2(acc[g], A, w2);
            }
        }
    }

    const int j  = j0 + ux;
    const int b  = b0 + rg * 2;
    float pl[4], ph[4];
    #pragma unroll
    for (int g = 0; g < 4; g++) {
        float bb = bias[g * E_ + j];
        pl[g] = lo2(acc[g]) + bb + pregate[(size_t)b * NCOL + g * E_ + j];
        ph[g] = hi2(acc[g]) + bb + pregate[(size_t)(b + 1) * NCOL + g * E_ + j];
    }
    {
        float ig = sigf(pl[0]), fg = sigf(pl[1]), cg = tanhf(pl[2]), og = sigf(pl[3]);
        float cn = fg * c_state[b * E_ + j] + ig * cg;
        c_state[b * E_ + j] = cn;
        h_out[b * E_ + j]   = og * tanhf(cn);
    }
    {
        float ig = sigf(ph[0]), fg = sigf(ph[1]), cg = tanhf(ph[2]), og = sigf(ph[3]);
        float cn = fg * c_state[(b + 1) * E_ + j] + ig * cg;
        c_state[(b + 1) * E_ + j] = cn;
        h_out[(b + 1) * E_ + j]   = og * tanhf(cn);
    }
}

// ---------------------------------------------------------------------------
// Persistent kernel: T=256 recurrence, 6 phases/step, grid barriers.
// ---------------------------------------------------------------------------
__global__ void __launch_bounds__(NTHREADS, 1) vae_persistent(VaeParams p)
{
    __shared__ __align__(16) float w_s[KT * 128];   // 16 KB
    __shared__ __align__(16) float a_s[KT * 64];    // 8 KB

    float* s = g_scratch;
    float* eh0[2] = { s + OFF_EH0, s + OFF_EH0 + HB };
    float* eh1[2] = { s + OFF_EH1, s + OFF_EH1 + HB };
    float* dh0[2] = { s + OFF_DH0, s + OFF_DH0 + HB };
    float* dh1[2] = { s + OFF_DH1, s + OFF_DH1 + HB };
    float* ec0  = s + OFF_EC0;
    float* ec1  = s + OFF_EC1;
    float* dc0  = s + OFF_DC0;
    float* dc1  = s + OFF_DC1;
    float* gU1  = s + OFF_GU1;
    float* gUd0 = s + OFF_GUD0;
    float* gUd1 = s + OFF_GUD1;
    float* encin = s + OFF_ENCIN;
    float* zbuf  = s + OFF_ZBUF;

    const int cta = blockIdx.x;
    const int tid = threadIdx.x;
    const int ux  = tid & 31;
    const int rg  = tid >> 5;
    int lgen = 0;

    // init: enc_in for t=0 (c_prev = 0 -> sigmoid = 0.5)
    {
        int idx = cta * NTHREADS + tid;
        if (idx < B_ * D_) {
            int b = idx >> 7, j = idx & 127;
            float xn = p.x[(size_t)b * T_ * D_ + j];
            encin[b * 256 + j]       = xn;
            encin[b * 256 + 128 + j] = xn - 0.5f;
        }
    }
    grid_sync(lgen);

    for (int t = 0; t < T_; t++) {
        const int pp = t & 1, q = pp ^ 1;

        // ---- Phase A: 3 recurrent U-GEMMs + fused enc0 (128 tiles = grid) ----
        {
            const int z   = cta >> 5;          // 0..3
            const int sub = cta & 31;
            const int b0  = (sub >> 4) * 64;   // 2 row tiles of 64
            const int j0  = (sub & 15) * 32;   // 16 col tiles

            unsigned long long acc[4][4];
            #pragma unroll
            for (int r = 0; r < 4; r++)
                #pragma unroll
                for (int g = 0; g < 4; g++) acc[r][g] = 0ull;

            const float *ga1, *gW1, *ga2, *gW2; int gK1, gK2;
            if (z == 0)      { ga1 = eh1[pp]; gW1 = p.enc1_U; gK1 = E_;  ga2 = nullptr; gW2 = nullptr; gK2 = 0; }
            else if (z == 1) { ga1 = dh0[pp]; gW1 = p.dec0_U; gK1 = E_;  ga2 = nullptr; gW2 = nullptr; gK2 = 0; }
            else if (z == 2) { ga1 = dh1[pp]; gW1 = p.dec1_U; gK1 = E_;  ga2 = nullptr; gW2 = nullptr; gK2 = 0; }
            else             { ga1 = encin;   gW1 = p.enc0_W; gK1 = 256; ga2 = eh0[pp]; gW2 = p.enc0_U; gK2 = E_; }

            gemm64(ga1, gW1, gK1, ga2, gW2, gK2, j0, b0, acc, w_s, a_s);

            const int j = j0 + ux;
            if (z < 3) {
                float* o = (z == 0) ? gU1 : (z == 1) ? gUd0 : gUd1;
                #pragma unroll
                for (int pr = 0; pr < 4; pr++) {
                    int b = b0 + rg * 8 + pr * 2;
                    #pragma unroll
                    for (int g = 0; g < 4; g++) {
                        o[(size_t)b * NCOL + g * E_ + j]       = lo2(acc[pr][g]);
                        o[(size_t)(b + 1) * NCOL + g * E_ + j] = hi2(acc[pr][g]);
                    }
                }
            } else {
                float b_i = p.enc0_b[0 * E_ + j];
                float b_f = p.enc0_b[1 * E_ + j];
                float b_c = p.enc0_b[2 * E_ + j];
                float b_o = p.enc0_b[3 * E_ + j];
                #pragma unroll
                for (int pr = 0; pr < 4; pr++) {
                    int b = b0 + rg * 8 + pr * 2;
                    {
                        float ig = sigf(lo2(acc[pr][0]) + b_i);
                        float fg = sigf(lo2(acc[pr][1]) + b_f);
                        float cg = tanhf(lo2(acc[pr][2]) + b_c);
                        float og = sigf(lo2(acc[pr][3]) + b_o);
                        float cn = fg * ec0[b * E_ + j] + ig * cg;
                        ec0[b * E_ + j] = cn;
                        eh0[q][b * E_ + j] = og * tanhf(cn);
                    }
                    {
                        float ig = sigf(hi2(acc[pr][0]) + b_i);
                        float fg = sigf(hi2(acc[pr][1]) + b_f);
                        float cg = tanhf(hi2(acc[pr][2]) + b_c);
                        float og = sigf(hi2(acc[pr][3]) + b_o);
                        float cn = fg * ec0[(b + 1) * E_ + j] + ig * cg;
                        ec0[(b + 1) * E_ + j] = cn;
                        eh0[q][(b + 1) * E_ + j] = og * tanhf(cn);
                    }
                }
            }
        }
        grid_sync(lgen);

        // ---- Phase B: enc1 finish ----
        finish16(eh0[q], p.enc1_W, E_, gU1, p.enc1_b, eh1[q], ec1, w_s, a_s);
        grid_sync(lgen);

        // ---- Phase C: latent (16 CTAs) ----
        if (cta < 16) {
            float (*wc)[64] = (float(*)[64])w_s;
            float (*ac)[KT] = (float(*)[KT])a_s;
            const int j0 = (cta & 1) * 32;
            const int b0 = (cta >> 1) * 16;
            float acc[2][2] = {{0.f, 0.f}, {0.f, 0.f}};
            const float* a = eh1[q];
            for (int k0 = 0; k0 < E_; k0 += KT) {
                #pragma unroll
                for (int i = 0; i < 8; i++) {
                    int idx = tid + i * 256;
                    int kk = idx >> 6;
                    int lc = idx & 63;
                    int col = j0 + (lc & 31);
                    wc[kk][lc] = (lc & 32) ? p.sig_W[(k0 + kk) * Z_ + col]
                                           : p.mu_W[(k0 + kk) * Z_ + col];
                }
                #pragma unroll
                for (int i = 0; i < 2; i++) {
                    int idx = tid + i * 256;
                    ac[idx >> 5][idx & 31] = a[(b0 + (idx >> 5)) * E_ + k0 + (idx & 31)];
                }
                __syncthreads();
                #pragma unroll
                for (int kk = 0; kk < KT; kk++) {
                    float av0 = ac[rg * 2 + 0][kk];
                    float av1 = ac[rg * 2 + 1][kk];
                    float wm = wc[kk][ux];
                    float ws = wc[kk][32 + ux];
                    acc[0][0] += av0 * wm; acc[0][1] += av0 * ws;
                    acc[1][0] += av1 * wm; acc[1][1] += av1 * ws;
                }
                __syncthreads();
            }
            const int j = j0 + ux;
            #pragma unroll
            for (int r = 0; r < 2; r++) {
                int b = b0 + rg * 2 + r;
                float mu = acc[r][0] + p.mu_b[j];
                float ls = acc[r][1] + p.sig_b[j];
                float sg = expf(ls);
                float zv = mu + sg * p.eps[((size_t)t * B_ + b) * Z_ + j];
                size_t o = ((size_t)t * B_ + b) * Z_ + j;
                p.o_sig[o] = sg;
                p.o_mu[o]  = mu;
                p.o_ls[o]  = ls;
                p.o_z[o]   = zv;
                zbuf[b * Z_ + j] = zv;
            }
        }
        grid_sync(lgen);

        // ---- Phase D: dec0 finish (K=64) ----
        finish16(zbuf, p.dec0_W, Z_, gUd0, p.dec0_b, dh0[q], dc0, w_s, a_s);
        grid_sync(lgen);

        // ---- Phase E: dec1 finish ----
        finish16(dh0[q], p.dec1_W, E_, gUd1, p.dec1_b, dh1[q], dc1, w_s, a_s);
        grid_sync(lgen);

        // ---- Phase F: output + next-step enc_in (32 CTAs) ----
        if (cta < 32) {
            float (*wf)[32] = (float(*)[32])w_s;
            float (*af)[KT] = (float(*)[KT])a_s;
            const int c0 = (cta & 3) * 32;
            const int b0 = (cta >> 2) * 16;
            float acc2[2] = {0.f, 0.f};
            const float* a = dh1[q];
            for (int k0 = 0; k0 < E_; k0 += KT) {
                #pragma unroll
                for (int i = 0; i < 4; i++) {
                    int idx = tid + i * 256;
                    wf[idx >> 5][idx & 31] = p.out_W[(k0 + (idx >> 5)) * D_ + c0 + (idx & 31)];
                }
                #pragma unroll
                for (int i = 0; i < 2; i++) {
                    int idx = tid + i * 256;
                    af[idx >> 5][idx & 31] = a[(b0 + (idx >> 5)) * E_ + k0 + (idx & 31)];
                }
                __syncthreads();
                #pragma unroll
                for (int kk = 0; kk < KT; kk++) {
                    float w = wf[kk][ux];
                    acc2[0] += af[rg * 2 + 0][kk] * w;
                    acc2[1] += af[rg * 2 + 1][kk] * w;
                }
                __syncthreads();
            }
            const int j  = c0 + ux;
            const int tn = (t + 1 < T_) ? (t + 1) : t;
            #pragma unroll
            for (int r = 0; r < 2; r++) {
                int b = b0 + rg * 2 + r;
                float ct = sigf(acc2[r] + p.out_b[j]);
                p.o_dec[(size_t)b * T_ * D_ + (size_t)t * D_ + j] = ct;
                float xn = p.x[(size_t)b * T_ * D_ + (size_t)tn * D_ + j];
                encin[b * 256 + j]       = xn;
                encin[b * 256 + 128 + j] = xn - sigf(ct);
            }
        }
        grid_sync(lgen);
    }
}

extern "C" void kernel_launch(void* const* d_in, const int* in_sizes, int n_in,
                              void* d_out, int out_size)
{
    VaeParams p;
    p.x      = (const float*)d_in[0];
    p.eps    = (const float*)d_in[1];
    p.enc0_W = (const float*)d_in[2];
    p.enc0_U = (const float*)d_in[3];
    p.enc0_b = (const float*)d_in[4];
    p.enc1_W = (const float*)d_in[5];
    p.enc1_U = (const float*)d_in[6];
    p.enc1_b = (const float*)d_in[7];
    p.mu_W   = (const float*)d_in[8];
    p.mu_b   = (const float*)d_in[9];
    p.sig_W  = (const float*)d_in[10];
    p.sig_b  = (const float*)d_in[11];
    p.dec0_W = (const float*)d_in[12];
    p.dec0_U = (const float*)d_in[13];
    p.dec0_b = (const float*)d_in[14];
    p.dec1_W = (const float*)d_in[15];
    p.dec1_U = (const float*)d_in[16];
    p.dec1_b = (const float*)d_in[17];
    p.out_W  = (const float*)d_in[18];
    p.out_b  = (const float*)d_in[19];

    float* out = (float*)d_out;
    p.o_dec = out;
    p.o_sig = out + (size_t)B_ * T_ * D_;
    p.o_mu  = p.o_sig + (size_t)T_ * B_ * Z_;
    p.o_ls  = p.o_mu  + (size_t)T_ * B_ * Z_;
    p.o_z   = p.o_ls  + (size_t)T_ * B_ * Z_;

    float* s = nullptr;
    cudaGetSymbolAddress((void**)&s, g_scratch);

    cudaMemsetAsync(s, 0, sizeof(float) * (size_t)STATE_END, 0);

    void* kernelArgs[] = { (void*)&p };
    cudaError_t e = cudaLaunchCooperativeKernel(
        (void*)vae_persistent, dim3(NCTA), dim3(NTHREADS), kernelArgs, 0, (cudaStream_t)0);
    if (e != cudaSuccess) {
        (void)cudaGetLastError();
        vae_persistent<<<NCTA, NTHREADS>>>(p);
    }
}

// round 10
// speedup vs baseline: 1.3030x; 1.0019x over previous
#include <cuda_runtime.h>
#include <math.h>
#include <stdint.h>

// Problem dims
#define B_ 128
#define T_ 256
#define D_ 128
#define Z_ 64
#define E_ 512
#define NCOL 2048
#define KT 32

#define NCTA 128
#define NTHREADS 256

// ---------------- scratch layout (floats) ----------------
#define HB 65536
#define OFF_BAR 0
#define OFF_STATE 64
#define OFF_EH0 (OFF_STATE)
#define OFF_EH1 (OFF_EH0 + 2*HB)
#define OFF_DH0 (OFF_EH1 + 2*HB)
#define OFF_DH1 (OFF_DH0 + 2*HB)
#define OFF_EC0 (OFF_DH1 + 2*HB)
#define OFF_EC1 (OFF_EC0 + HB)
#define OFF_DC0 (OFF_EC1 + HB)
#define OFF_DC1 (OFF_DC0 + HB)
#define STATE_END (OFF_DC1 + HB)
#define OFF_GU1 STATE_END
#define OFF_GUD0 (OFF_GU1 + 262144)
#define OFF_GUD1 (OFF_GUD0 + 262144)
#define OFF_ENCIN (OFF_GUD1 + 262144)
#define OFF_ZBUF (OFF_ENCIN + 32768)
#define SCRATCH_TOTAL (OFF_ZBUF + 8192)

__device__ float g_scratch[SCRATCH_TOTAL];

__device__ __forceinline__ float sigf(float x) { return 1.0f / (1.0f + expf(-x)); }

// Packed f32x2 FMA (full-rate fp32 path on sm_103a; ptxas never auto-emits it)
#define FMA2(acc_, a_, b_) \
    asm("fma.rn.f32x2 %0, %1, %2, %0;" : "+l"(acc_) : "l"(a_), "l"(b_))

__device__ __forceinline__ unsigned long long splat2(float w) {
    unsigned long long r; unsigned int b = __float_as_uint(w);
    asm("mov.b64 %0, {%1, %1};" : "=l"(r) : "r"(b));
    return r;
}
__device__ __forceinline__ float lo2(unsigned long long v) { return __uint_as_float((unsigned)v); }
__device__ __forceinline__ float hi2(unsigned long long v) { return __uint_as_float((unsigned)(v >> 32)); }

struct VaeParams {
    const float *x, *eps;
    const float *enc0_W, *enc0_U, *enc0_b;
    const float *enc1_W, *enc1_U, *enc1_b;
    const float *mu_W, *mu_b, *sig_W, *sig_b;
    const float *dec0_W, *dec0_U, *dec0_b;
    const float *dec1_W, *dec1_U, *dec1_b;
    const float *out_W, *out_b;
    float *o_dec, *o_sig, *o_mu, *o_ls, *o_z;
};

// ---------------------------------------------------------------------------
// Grid barrier (state zeroed by the memset node every replay; co-residency
// guaranteed by cooperative launch, with plain-launch fallback).
// ---------------------------------------------------------------------------
__device__ __forceinline__ void grid_sync(int& lgen)
{
    int* bar = (int*)g_scratch;            // [0]=cnt, [1]=gen
    __threadfence();
    __syncthreads();
    if (threadIdx.x == 0) {
        volatile int* gen = bar + 1;
        int g = lgen;
        if (atomicAdd(bar, 1) == NCTA - 1) {
            *bar = 0;
            __threadfence();
            atomicExch((int*)(bar + 1), g + 1);
        } else {
            while (*gen <= g) { __nanosleep(64); }
        }
    }
    __syncthreads();
    __threadfence();
    lgen++;
}

// ---------------------------------------------------------------------------
// Phase-A GEMM: 64 rows x 128 cols (32 units x 4 gates) per CTA, 256 thr.
// Thread: 8 rows (4 f32x2 pairs) x 4 gates. Register-prefetch double buffer.
// a_s transposed [KT][64] with XOR swizzle on 4-float groups (2-way STS);
// w_s [KT][128] gate-grouped (conflict-free).
// ---------------------------------------------------------------------------
__device__ __forceinline__ void gemm64(
    const float* __restrict__ a1, const float* __restrict__ W1, int K1,
    const float* __restrict__ a2, const float* __restrict__ W2, int K2,
    int j0, int b0, unsigned long long acc[4][4],
    float* w_s, float* a_s)
{
    const int tid = threadIdx.x;
    const int ux  = tid & 31;
    const int rg  = tid >> 5;
    const int nt  = (K1 + K2) / KT;
    float wreg[16], areg[8];

    auto load_tile = [&](int t) {
        int kb = t * KT;
        const float* a = a1; const float* W = W1; int K = K1;
        if (kb >= K1) { a = a2; W = W2; K = K2; kb -= K1; }
        #pragma unroll
        for (int i = 0; i < 16; i++) {
            int idx = tid + i * 256;
            wreg[i] = W[(kb + (idx >> 7)) * NCOL + (((idx & 127) >> 5) * E_ + j0 + (idx & 31))];
        }
        #pragma unroll
        for (int i = 0; i < 8; i++) {
            int idx = tid + i * 256;
            areg[i] = a[(b0 + (idx >> 5)) * K + kb + (idx & 31)];
        }
    };

    load_tile(0);
    #pragma unroll 1
    for (int t = 0; t < nt; t++) {
        __syncthreads();
        #pragma unroll
        for (int i = 0; i < 16; i++) {
            int idx = tid + i * 256;
            w_s[(idx >> 7) * 128 + (idx & 127)] = wreg[i];
        }
        #pragma unroll
        for (int i = 0; i < 8; i++) {
            int idx = tid + i * 256;
            int kk = idx & 31, row = idx >> 5;
            a_s[kk * 64 + (((row >> 2) ^ (kk & 15)) << 2) + (row & 3)] = areg[i];
        }
        __syncthreads();
        if (t + 1 < nt) load_tile(t + 1);
        #pragma unroll 8
        for (int kk = 0; kk < KT; kk++) {
            const float* ak = a_s + kk * 64;
            const int sw = kk & 15;
            ulonglong2 A0 = *(const ulonglong2*)(ak + (((rg * 2 + 0) ^ sw) << 2));
            ulonglong2 A1 = *(const ulonglong2*)(ak + (((rg * 2 + 1) ^ sw) << 2));
            const float* wk = w_s + kk * 128 + ux;
            #pragma unroll
            for (int g = 0; g < 4; g++) {
                unsigned long long w2 = splat2(wk[g * 32]);
                FMA2(acc[0][g], A0.x, w2);
                FMA2(acc[1][g], A0.y, w2);
                FMA2(acc[2][g], A1.x, w2);
                FMA2(acc[3][g], A1.y, w2);
            }
        }
    }
}

// ---------------------------------------------------------------------------
// Finish stage: 16 rows x 128 cols per CTA (128 CTAs). Thread: 1 pair x 4
// gates. W-GEMM + pregate + bias + LSTM update. Register-prefetch buffered.
// ---------------------------------------------------------------------------
__device__ __noinline__ void finish16(
    const float* __restrict__ a, const float* __restrict__ W, int K,
    const float* __restrict__ pregate, const float* __restrict__ bias,
    float* __restrict__ h_out, float* __restrict__ c_state,
    float* w_s, float* a_s)
{
    const int tid = threadIdx.x;
    const int ux  = tid & 31;
    const int rg  = tid >> 5;
    const int cta = blockIdx.x;
    const int j0  = (cta & 15) * 32;
    const int b0  = (cta >> 4) * 16;
    const int nt  = K / KT;
    unsigned long long acc[4] = {0ull, 0ull, 0ull, 0ull};
    float wreg[16], areg[2];

    auto load_tile = [&](int t) {
        int kb = t * KT;
        #pragma unroll
        for (int i = 0; i < 16; i++) {
            int idx = tid + i * 256;
            wreg[i] = W[(kb + (idx >> 7)) * NCOL + (((idx & 127) >> 5) * E_ + j0 + (idx & 31))];
        }
        #pragma unroll
        for (int i = 0; i < 2; i++) {
            int idx = tid + i * 256;
            areg[i] = a[(b0 + (idx & 15)) * K + kb + (idx >> 4)];
        }
    };

    load_tile(0);
    #pragma unroll 1
    for (int t = 0; t < nt; t++) {
        __syncthreads();
        #pragma unroll
        for (int i = 0; i < 16; i++) {
            int idx = tid + i * 256;
            w_s[(idx >> 7) * 128 + (idx & 127)] = wreg[i];
        }
        #pragma unroll
        for (int i = 0; i < 2; i++) {
            int idx = tid + i * 256;
            int kk = idx >> 4, row = idx & 15;
            a_s[kk * 16 + (((row >> 2) ^ (kk & 3)) << 2) + (row & 3)] = areg[i];
        }
        __syncthreads();
        if (t + 1 < nt) load_tile(t + 1);
        #pragma unroll 8
        for (int kk = 0; kk < KT; kk++) {
            unsigned long long A = *(const unsigned long long*)(
                a_s + kk * 16 + ((((rg >> 1) ^ (kk & 3))) << 2) + ((rg & 1) << 1));
            const float* wk = w_s + kk * 128 + ux;
            #pragma unroll
            for (int g = 0; g < 4; g++) {
                unsigned long long w2 = splat2(wk[g * 32]);
                FMA2(acc[g], A, w2);
            }
        }
    }

    const int j  = j0 + ux;
    const int b  = b0 + rg * 2;
    float pl[4], ph[4];
    #pragma unroll
    for (int g = 0; g < 4; g++) {
        float bb = bias[g * E_ + j];
        pl[g] = lo2(acc[g]) + bb + pregate[(size_t)b * NCOL + g * E_ + j];
        ph[g] = hi2(acc[g]) + bb + pregate[(size_t)(b + 1) * NCOL + g * E_ + j];
    }
    {
        float ig = sigf(pl[0]), fg = sigf(pl[1]), cg = tanhf(pl[2]), og = sigf(pl[3]);
        float cn = fg * c_state[b * E_ + j] + ig * cg;
        c_state[b * E_ + j] = cn;
        h_out[b * E_ + j]   = og * tanhf(cn);
    }
    {
        float ig = sigf(ph[0]), fg = sigf(ph[1]), cg = tanhf(ph[2]), og = sigf(ph[3]);
        float cn = fg * c_state[(b + 1) * E_ + j] + ig * cg;
        c_state[(b + 1) * E_ + j] = cn;
        h_out[(b + 1) * E_ + j]   = og * tanhf(cn);
    }
}

// ---------------------------------------------------------------------------
// Persistent kernel: T=256 recurrence, 6 phases/step, grid barriers.
// ---------------------------------------------------------------------------
__global__ void __launch_bounds__(NTHREADS, 1) vae_persistent(VaeParams p)
{
    __shared__ __align__(16) float w_s[KT * 128];   // 16 KB
    __shared__ __align__(16) float a_s[KT * 64];    // 8 KB

    float* s = g_scratch;
    float* eh0[2] = { s + OFF_EH0, s + OFF_EH0 + HB };
    float* eh1[2] = { s + OFF_EH1, s + OFF_EH1 + HB };
    float* dh0[2] = { s + OFF_DH0, s + OFF_DH0 + HB };
    float* dh1[2] = { s + OFF_DH1, s + OFF_DH1 + HB };
    float* ec0  = s + OFF_EC0;
    float* ec1  = s + OFF_EC1;
    float* dc0  = s + OFF_DC0;
    float* dc1  = s + OFF_DC1;
    float* gU1  = s + OFF_GU1;
    float* gUd0 = s + OFF_GUD0;
    float* gUd1 = s + OFF_GUD1;
    float* encin = s + OFF_ENCIN;
    float* zbuf  = s + OFF_ZBUF;

    const int cta = blockIdx.x;
    const int tid = threadIdx.x;
    const int ux  = tid & 31;
    const int rg  = tid >> 5;
    int lgen = 0;

    // init: enc_in for t=0 (c_prev = 0 -> sigmoid = 0.5)
    {
        int idx = cta * NTHREADS + tid;
        if (idx < B_ * D_) {
            int b = idx >> 7, j = idx & 127;
            float xn = p.x[(size_t)b * T_ * D_ + j];
            encin[b * 256 + j]       = xn;
            encin[b * 256 + 128 + j] = xn - 0.5f;
        }
    }
    grid_sync(lgen);

    for (int t = 0; t < T_; t++) {
        const int pp = t & 1, q = pp ^ 1;

        // ---- Phase A: 3 recurrent U-GEMMs + fused enc0 (128 tiles = grid) ----
        {
            const int z   = cta >> 5;          // 0..3
            const int sub = cta & 31;
            const int b0  = (sub >> 4) * 64;   // 2 row tiles of 64
            const int j0  = (sub & 15) * 32;   // 16 col tiles

            unsigned long long acc[4][4];
            #pragma unroll
            for (int r = 0; r < 4; r++)
                #pragma unroll
                for (int g = 0; g < 4; g++) acc[r][g] = 0ull;

            const float *ga1, *gW1, *ga2, *gW2; int gK1, gK2;
            if (z == 0)      { ga1 = eh1[pp]; gW1 = p.enc1_U; gK1 = E_;  ga2 = nullptr; gW2 = nullptr; gK2 = 0; }
            else if (z == 1) { ga1 = dh0[pp]; gW1 = p.dec0_U; gK1 = E_;  ga2 = nullptr; gW2 = nullptr; gK2 = 0; }
            else if (z == 2) { ga1 = dh1[pp]; gW1 = p.dec1_U; gK1 = E_;  ga2 = nullptr; gW2 = nullptr; gK2 = 0; }
            else             { ga1 = encin;   gW1 = p.enc0_W; gK1 = 256; ga2 = eh0[pp]; gW2 = p.enc0_U; gK2 = E_; }

            gemm64(ga1, gW1, gK1, ga2, gW2, gK2, j0, b0, acc, w_s, a_s);

            const int j = j0 + ux;
            if (z < 3) {
                float* o = (z == 0) ? gU1 : (z == 1) ? gUd0 : gUd1;
                #pragma unroll
                for (int pr = 0; pr < 4; pr++) {
                    int b = b0 + rg * 8 + pr * 2;
                    #pragma unroll
                    for (int g = 0; g < 4; g++) {
                        o[(size_t)b * NCOL + g * E_ + j]       = lo2(acc[pr][g]);
                        o[(size_t)(b + 1) * NCOL + g * E_ + j] = hi2(acc[pr][g]);
                    }
                }
            } else {
                float b_i = p.enc0_b[0 * E_ + j];
                float b_f = p.enc0_b[1 * E_ + j];
                float b_c = p.enc0_b[2 * E_ + j];
                float b_o = p.enc0_b[3 * E_ + j];
                #pragma unroll
                for (int pr = 0; pr < 4; pr++) {
                    int b = b0 + rg * 8 + pr * 2;
                    {
                        float ig = sigf(lo2(acc[pr][0]) + b_i);
                        float fg = sigf(lo2(acc[pr][1]) + b_f);
                        float cg = tanhf(lo2(acc[pr][2]) + b_c);
                        float og = sigf(lo2(acc[pr][3]) + b_o);
                        float cn = fg * ec0[b * E_ + j] + ig * cg;
                        ec0[b * E_ + j] = cn;
                        eh0[q][b * E_ + j] = og * tanhf(cn);
                    }
                    {
                        float ig = sigf(hi2(acc[pr][0]) + b_i);
                        float fg = sigf(hi2(acc[pr][1]) + b_f);
                        float cg = tanhf(hi2(acc[pr][2]) + b_c);
                        float og = sigf(hi2(acc[pr][3]) + b_o);
                        float cn = fg * ec0[(b + 1) * E_ + j] + ig * cg;
                        ec0[(b + 1) * E_ + j] = cn;
                        eh0[q][(b + 1) * E_ + j] = og * tanhf(cn);
                    }
                }
            }
        }
        grid_sync(lgen);

        // ---- Phase B: enc1 finish ----
        finish16(eh0[q], p.enc1_W, E_, gU1, p.enc1_b, eh1[q], ec1, w_s, a_s);
        grid_sync(lgen);

        // ---- Phase C: latent (16 CTAs) ----
        if (cta < 16) {
            float (*wc)[64] = (float(*)[64])w_s;
            float (*ac)[KT] = (float(*)[KT])a_s;
            const int j0 = (cta & 1) * 32;
            const int b0 = (cta >> 1) * 16;
            float acc[2][2] = {{0.f, 0.f}, {0.f, 0.f}};
            const float* a = eh1[q];
            for (int k0 = 0; k0 < E_; k0 += KT) {
                #pragma unroll
                for (int i = 0; i < 8; i++) {
                    int idx = tid + i * 256;
                    int kk = idx >> 6;
                    int lc = idx & 63;
                    int col = j0 + (lc & 31);
                    wc[kk][lc] = (lc & 32) ? p.sig_W[(k0 + kk) * Z_ + col]
                                           : p.mu_W[(k0 + kk) * Z_ + col];
                }
                #pragma unroll
                for (int i = 0; i < 2; i++) {
                    int idx = tid + i * 256;
                    ac[idx >> 5][idx & 31] = a[(b0 + (idx >> 5)) * E_ + k0 + (idx & 31)];
                }
                __syncthreads();
                #pragma unroll
                for (int kk = 0; kk < KT; kk++) {
                    float av0 = ac[rg * 2 + 0][kk];
                    float av1 = ac[rg * 2 + 1][kk];
                    float wm = wc[kk][ux];
                    float ws = wc[kk][32 + ux];
                    acc[0][0] += av0 * wm; acc[0][1] += av0 * ws;
                    acc[1][0] += av1 * wm; acc[1][1] += av1 * ws;
                }
                __syncthreads();
            }
            const int j = j0 + ux;
            #pragma unroll
            for (int r = 0; r < 2; r++) {
                int b = b0 + rg * 2 + r;
                float mu = acc[r][0] + p.mu_b[j];
                float ls = acc[r][1] + p.sig_b[j];
                float sg = expf(ls);
                float zv = mu + sg * p.eps[((size_t)t * B_ + b) * Z_ + j];
                size_t o = ((size_t)t * B_ + b) * Z_ + j;
                p.o_sig[o] = sg;
                p.o_mu[o]  = mu;
                p.o_ls[o]  = ls;
                p.o_z[o]   = zv;
                zbuf[b * Z_ + j] = zv;
            }
        }
        grid_sync(lgen);

        // ---- Phase D: dec0 finish (K=64) ----
        finish16(zbuf, p.dec0_W, Z_, gUd0, p.dec0_b, dh0[q], dc0, w_s, a_s);
        grid_sync(lgen);

        // ---- Phase E: dec1 finish ----
        finish16(dh0[q], p.dec1_W, E_, gUd1, p.dec1_b, dh1[q], dc1, w_s, a_s);
        grid_sync(lgen);

        // ---- Phase F: output + next-step enc_in (32 CTAs) ----
        if (cta < 32) {
            float (*wf)[32] = (float(*)[32])w_s;
            float (*af)[KT] = (float(*)[KT])a_s;
            const int c0 = (cta & 3) * 32;
            const int b0 = (cta >> 2) * 16;
            float acc2[2] = {0.f, 0.f};
            const float* a = dh1[q];
            for (int k0 = 0; k0 < E_; k0 += KT) {
                #pragma unroll
                for (int i = 0; i < 4; i++) {
                    int idx = tid + i * 256;
                    wf[idx >> 5][idx & 31] = p.out_W[(k0 + (idx >> 5)) * D_ + c0 + (idx & 31)];
                }
                #pragma unroll
                for (int i = 0; i < 2; i++) {
                    int idx = tid + i * 256;
                    af[idx >> 5][idx & 31] = a[(b0 + (idx >> 5)) * E_ + k0 + (idx & 31)];
                }
                __syncthreads();
                #pragma unroll
                for (int kk = 0; kk < KT; kk++) {
                    float w = wf[kk][ux];
                    acc2[0] += af[rg * 2 + 0][kk] * w;
                    acc2[1] += af[rg * 2 + 1][kk] * w;
                }
                __syncthreads();
            }
            const int j  = c0 + ux;
            const int tn = (t + 1 < T_) ? (t + 1) : t;
            #pragma unroll
            for (int r = 0; r < 2; r++) {
                int b = b0 + rg * 2 + r;
                float ct = sigf(acc2[r] + p.out_b[j]);
                p.o_dec[(size_t)b * T_ * D_ + (size_t)t * D_ + j] = ct;
                float xn = p.x[(size_t)b * T_ * D_ + (size_t)tn * D_ + j];
                encin[b * 256 + j]       = xn;
                encin[b * 256 + 128 + j] = xn - sigf(ct);
            }
        }
        grid_sync(lgen);
    }
}

extern "C" void kernel_launch(void* const* d_in, const int* in_sizes, int n_in,
                              void* d_out, int out_size)
{
    VaeParams p;
    p.x      = (const float*)d_in[0];
    p.eps    = (const float*)d_in[1];
    p.enc0_W = (const float*)d_in[2];
    p.enc0_U = (const float*)d_in[3];
    p.enc0_b = (const float*)d_in[4];
    p.enc1_W = (const float*)d_in[5];
    p.enc1_U = (const float*)d_in[6];
    p.enc1_b = (const float*)d_in[7];
    p.mu_W   = (const float*)d_in[8];
    p.mu_b   = (const float*)d_in[9];
    p.sig_W  = (const float*)d_in[10];
    p.sig_b  = (const float*)d_in[11];
    p.dec0_W = (const float*)d_in[12];
    p.dec0_U = (const float*)d_in[13];
    p.dec0_b = (const float*)d_in[14];
    p.dec1_W = (const float*)d_in[15];
    p.dec1_U = (const float*)d_in[16];
    p.dec1_b = (const float*)d_in[17];
    p.out_W  = (const float*)d_in[18];
    p.out_b  = (const float*)d_in[19];

    float* out = (float*)d_out;
    p.o_dec = out;
    p.o_sig = out + (size_t)B_ * T_ * D_;
    p.o_mu  = p.o_sig + (size_t)T_ * B_ * Z_;
    p.o_ls  = p.o_mu  + (size_t)T_ * B_ * Z_;
    p.o_z   = p.o_ls  + (size_t)T_ * B_ * Z_;

    float* s = nullptr;
    cudaGetSymbolAddress((void**)&s, g_scratch);

    cudaMemsetAsync(s, 0, sizeof(float) * (size_t)STATE_END, 0);

    void* kernelArgs[] = { (void*)&p };
    cudaError_t e = cudaLaunchCooperativeKernel(
        (void*)vae_persistent, dim3(NCTA), dim3(NTHREADS), kernelArgs, 0, (cudaStream_t)0);
    if (e != cudaSuccess) {
        (void)cudaGetLastError();
        vae_persistent<<<NCTA, NTHREADS>>>(p);
    }
}